// round 16
// baseline (speedup 1.0000x reference)
#include <cuda_runtime.h>
#include <math.h>

#define B 8
#define N 1024
#define C 256
#define K 256
#define C2 512
#define SCALE 0.17677669529663687f   // (C/H)^-0.5 = 1/sqrt(32)

// Output layout: [new_X (8*256*256) | new_adj (8*256*256) | new_mask (8*256)]
#define OUT_ADJ_OFF  (B*K*C)
#define OUT_MASK_OFF (2*B*K*C)

#define NCHUNK 64      // partial-sum chunks per batch (16 rows each)

// ---- scratch ----
__device__ float d_part[B*NCHUNK*C];
__device__ float d_u[B*C];
__device__ float d_scores[B*N];
__device__ int   d_idxg[B*K];
__device__ float d_gate[B*K];
__device__ float d_nm[B*K];

// ---------------------------------------------------------------------------
// K1: partial column sums of X (verbatim R2 — proven rounding).
// ---------------------------------------------------------------------------
__global__ void k_partial(const float* __restrict__ X) {
    int b = blockIdx.y, ch = blockIdx.x, c = threadIdx.x;
    const float* xp = X + ((size_t)b * N + (size_t)ch * 16) * C + c;
    float s = 0.f;
    #pragma unroll
    for (int r = 0; r < 16; r++) s += xp[(size_t)r * C];
    d_part[(b * NCHUNK + ch) * C + c] = s;
}

// ---------------------------------------------------------------------------
// K2: Xsum finish + two matvecs (R2 arithmetic order, unroll hints only —
// single accumulator per loop keeps summation order bit-identical).
// ---------------------------------------------------------------------------
__global__ void k_uvec(const float* __restrict__ Wqkv) {
    int b = blockIdx.x, t = threadIdx.x;
    __shared__ float xs[C];
    __shared__ float ks[C];
    float s = 0.f;
    #pragma unroll
    for (int ch = 0; ch < NCHUNK; ch++) s += d_part[(b * NCHUNK + ch) * C + t];
    xs[t] = s;
    __syncthreads();
    float ka = 0.f;
    #pragma unroll 8
    for (int c = 0; c < C; c++) ka += xs[c] * Wqkv[(size_t)c * C2 + C + t];
    ks[t] = ka;
    __syncthreads();
    const float* wrow = Wqkv + (size_t)t * C2;
    float ua = 0.f;
    #pragma unroll 8
    for (int j = 0; j < C; j++) ua += wrow[j] * ks[j];
    d_u[b * C + t] = ua;
}

// ---------------------------------------------------------------------------
// K3: scores (verbatim R2 — proven rounding).
// ---------------------------------------------------------------------------
__global__ void k_scores(const float* __restrict__ X,
                         const float* __restrict__ mask) {
    int b = blockIdx.y, t = threadIdx.x;
    __shared__ float us[C];
    us[t] = d_u[b * C + t];
    __syncthreads();
    int warp = t >> 5, lane = t & 31;
    int n = blockIdx.x * 8 + warp;
    const float4* xr = (const float4*)(X + ((size_t)b * N + n) * C);
    const float4* ur = (const float4*)us;
    float acc = 0.f;
    #pragma unroll
    for (int it = 0; it < 2; it++) {
        float4 xv = xr[lane + it * 32];
        float4 uv = ur[lane + it * 32];
        acc += xv.x * uv.x + xv.y * uv.y + xv.z * uv.z + xv.w * uv.w;
    }
    #pragma unroll
    for (int o = 16; o; o >>= 1) acc += __shfl_xor_sync(0xffffffffu, acc, o);
    if (lane == 0) {
        float m = mask[b * N + n];
        d_scores[b * N + n] = (m > 0.f) ? SCALE * acc : -1e9f;
    }
}

// ---------------------------------------------------------------------------
// K4: top-k (verbatim R13/R15 — best measured top-k, 8.8us, proven).
// Virtual-processor bitonic: 256 threads x 4 elements, e = t + 256*m.
// ---------------------------------------------------------------------------
__global__ void __launch_bounds__(256, 1)
k_topk(const float* __restrict__ mask, float* __restrict__ out) {
    int b = blockIdx.x, t = threadIdx.x;
    __shared__ unsigned long long sx[4][256];
    __shared__ float red[8];
    __shared__ int s_ki;

    unsigned long long v[4];
    float msum = 0.f;
    #pragma unroll
    for (int m = 0; m < 4; m++) {
        int e = t + 256 * m;
        float f = d_scores[b * N + e];
        unsigned u = __float_as_uint(f);
        u = (u & 0x80000000u) ? ~u : (u | 0x80000000u);
        v[m] = ((unsigned long long)(~u) << 32) | (unsigned)e;
        msum += mask[b * N + e];
    }
    #pragma unroll
    for (int o = 16; o; o >>= 1) msum += __shfl_xor_sync(0xffffffffu, msum, o);
    if ((t & 31) == 0) red[t >> 5] = msum;
    __syncthreads();
    if (t == 0) {
        float s = 0.f;
        #pragma unroll
        for (int w = 0; w < 8; w++) s += red[w];
        s_ki = (int)ceilf(0.25f * s);
    }
    __syncthreads();

    #pragma unroll
    for (unsigned k = 2; k <= 1024; k <<= 1) {
        #pragma unroll
        for (unsigned j = 512; j > 0; j >>= 1) {
            if (j > (k >> 1)) continue;
            if (j >= 256) {
                int jm = (int)(j >> 8);
                #pragma unroll
                for (int m = 0; m < 4; m++) {
                    if ((m & jm) == 0) {
                        int mp = m | jm;
                        bool up = (k == 1024) ? true : ((m & 2) == 0);
                        unsigned long long a = v[m], bb = v[mp];
                        unsigned long long mn = a < bb ? a : bb;
                        unsigned long long mx = a < bb ? bb : a;
                        v[m]  = up ? mn : mx;
                        v[mp] = up ? mx : mn;
                    }
                }
            } else if (j >= 32) {
                #pragma unroll
                for (int m = 0; m < 4; m++) sx[m][t] = v[m];
                __syncthreads();
                bool lower = ((t & j) == 0);
                #pragma unroll
                for (int m = 0; m < 4; m++) {
                    bool up;
                    if (k <= 128)       up = ((t & k) == 0);
                    else if (k == 256)  up = ((m & 1) == 0);
                    else if (k == 512)  up = ((m & 2) == 0);
                    else                up = true;
                    unsigned long long w = sx[m][t ^ j];
                    bool takeMin = (lower == up);
                    v[m] = takeMin ? (v[m] < w ? v[m] : w)
                                   : (v[m] > w ? v[m] : w);
                }
                __syncthreads();
            } else {
                bool lower = ((t & j) == 0);
                #pragma unroll
                for (int m = 0; m < 4; m++) {
                    bool up;
                    if (k <= 128)       up = ((t & k) == 0);
                    else if (k == 256)  up = ((m & 1) == 0);
                    else if (k == 512)  up = ((m & 2) == 0);
                    else                up = true;
                    unsigned long long w = __shfl_xor_sync(0xffffffffu, v[m], j);
                    bool takeMin = (lower == up);
                    v[m] = takeMin ? (v[m] < w ? v[m] : w)
                                   : (v[m] > w ? v[m] : w);
                }
            }
        }
    }

    {
        unsigned long long key = v[0];
        int n = (int)(unsigned)key;
        unsigned uh = ~(unsigned)(key >> 32);
        unsigned orig = (uh & 0x80000000u) ? (uh & 0x7fffffffu) : ~uh;
        float val = __uint_as_float(orig);
        float nm = (t < s_ki) ? 1.f : 0.f;
        d_idxg[b * K + t] = n;
        d_gate[b * K + t] = tanhf(val) * nm;
        d_nm[b * K + t]   = nm;
        out[OUT_MASK_OFF + b * K + t] = nm;
    }
}

// ---------------------------------------------------------------------------
// K5: gather, 8 rows per block, pipelined. grid (32, 8), 256 threads.
//   new_X[b,i,:]   = X[b, idx[i], :] * gate[i]          (coalesced)
//   new_adj[b,i,j] = adj[b, idx[i], idx[j]] * nm[i]*nm[j]
// 8 adj rows (32KB) staged with 8 independent float4 loads in flight per
// thread; uniform scalars loaded direct from gmem before the single barrier;
// sidx/snm staging amortized over 8 output rows.
// ---------------------------------------------------------------------------
__global__ void k_gather(const float* __restrict__ X,
                         const float* __restrict__ adj,
                         float* __restrict__ out) {
    int b = blockIdx.y, i0 = blockIdx.x * 8, t = threadIdx.x;
    __shared__ int   sidx[K];
    __shared__ float snm[K];
    __shared__ __align__(16) float srow[8][N];   // 32KB

    // uniform per-block scalars straight from gmem — no barrier dependency
    int   ri[8];
    float nmi[8], gte[8];
    #pragma unroll
    for (int r = 0; r < 8; r++) {
        ri[r]  = d_idxg[b * K + i0 + r];
        nmi[r] = d_nm[b * K + i0 + r];
        gte[r] = d_gate[b * K + i0 + r];
    }
    // stage index/mask vectors concurrently with the row loads below
    sidx[t] = d_idxg[b * K + t];
    snm[t]  = d_nm[b * K + t];

    // 8 adj rows coalesced — 8 independent LDG.128 in flight per thread
    const float* adjb = adj + (size_t)b * N * N;
    #pragma unroll
    for (int r = 0; r < 8; r++) {
        const float4* src = (const float4*)(adjb + (size_t)ri[r] * N);
        ((float4*)srow[r])[t] = src[t];
    }
    // new_X rows (coalesced), overlapped with adj staging
    #pragma unroll
    for (int r = 0; r < 8; r++) {
        out[((size_t)b * K + i0 + r) * C + t] =
            X[((size_t)b * N + ri[r]) * C + t] * gte[r];
    }
    __syncthreads();

    int   cj  = sidx[t];
    float nmj = snm[t];
    #pragma unroll
    for (int r = 0; r < 8; r++) {
        out[OUT_ADJ_OFF + ((size_t)b * K + i0 + r) * K + t] =
            srow[r][cj] * nmi[r] * nmj;
    }
}

// ---------------------------------------------------------------------------
extern "C" void kernel_launch(void* const* d_in, const int* in_sizes, int n_in,
                              void* d_out, int out_size) {
    const float* X    = (const float*)d_in[0];
    const float* adj  = (const float*)d_in[1];
    const float* mask = (const float*)d_in[2];
    const float* Wqkv = (const float*)d_in[3];
    float* out = (float*)d_out;

    k_partial<<<dim3(NCHUNK, B), 256>>>(X);
    k_uvec<<<B, 256>>>(Wqkv);
    k_scores<<<dim3(N / 8, B), 256>>>(X, mask);
    k_topk<<<B, 256>>>(mask, out);
    k_gather<<<dim3(K / 8, B), 256>>>(X, adj, out);
}